// round 4
// baseline (speedup 1.0000x reference)
#include <cuda_runtime.h>

#define NUM_ENT   14541
#define EMBED_D   200
#define D2        100
#define D2_HALF   50
#define BATCH     256
#define TILE_B    64
#define TILE_N    131          // 111 * 131 == 14541 exactly
#define N_TILES   111
#define B_TILES   4
#define THREADS   512
#define OBJ_PITCH 65
#define ENT_PITCH 131
#define SMEM_ULL  (D2 * ENT_PITCH + D2 * OBJ_PITCH)   // 19600
#define SMEM_BYTES (SMEM_ULL * 8)                      // 156800

typedef unsigned long long ull;

__device__ float g_obj[BATCH * EMBED_D];

__global__ void obj_kernel(const float* __restrict__ ent,
                           const float* __restrict__ rel_e,
                           const int* __restrict__ sub,
                           const int* __restrict__ rel) {
    int idx = blockIdx.x * blockDim.x + threadIdx.x;
    if (idx < BATCH * EMBED_D) {
        int b = idx / EMBED_D;
        int d = idx - b * EMBED_D;
        g_obj[idx] = ent[sub[b] * EMBED_D + d] + rel_e[rel[b] * EMBED_D + d];
    }
}

__device__ __forceinline__ ull addf2(ull a, ull b) {
    ull r;
    asm("add.rn.f32x2 %0, %1, %2;" : "=l"(r) : "l"(a), "l"(b));
    return r;
}

// One pipeline step: F(diff_k), A(lo-and_{k-2}), F(acc_{k-4}), A(hi-and_{k-2})
// Strict fma/alu alternation; all producer->consumer distances >= 9 slots.
#define KSTEP(k, doA, doAcc)                                                  \
    {                                                                         \
        asm volatile("add.rn.f32x2 %0, %1, %2;"                               \
                     : "=l"(t[(k) & 3]) : "l"(o[(k) >> 2]), "l"(e[(k) & 3])); \
        if (doA) {                                                            \
            unsigned lo_, hi_;                                                \
            asm("mov.b64 {%0, %1}, %2;"                                       \
                : "=r"(lo_), "=r"(hi_) : "l"(t[((k) + 2) & 3]));              \
            asm volatile("and.b32 %0, %1, 0x7fffffff;"                        \
                         : "=r"(u_lo[((k) + 2) & 3]) : "r"(lo_));             \
            if (doAcc) {                                                      \
                ull uu_;                                                      \
                asm("mov.b64 %0, {%1, %2};"                                   \
                    : "=l"(uu_) : "r"(u_lo[(k) & 3]), "r"(u_hi[(k) & 3]));    \
                asm volatile("add.rn.f32x2 %0, %0, %1;"                       \
                             : "+l"(acc[((k) + 28) & 31]) : "l"(uu_));        \
            }                                                                 \
            asm volatile("and.b32 %0, %1, 0x7fffffff;"                        \
                         : "=r"(u_hi[((k) + 2) & 3]) : "r"(hi_));             \
        }                                                                     \
    }

__global__ void __launch_bounds__(THREADS, 1)
transe_kernel(const float* __restrict__ ent, float* __restrict__ out) {
    extern __shared__ ull smem[];
    ull* ent_s = smem;                     // [D2][ENT_PITCH], pre-negated
    ull* obj_s = smem + D2 * ENT_PITCH;    // [D2][OBJ_PITCH]

    const int tid = threadIdx.x;
    const int n0  = blockIdx.x * TILE_N;
    const int b0  = blockIdx.y * TILE_B;

    for (int idx = tid; idx < TILE_N * D2; idx += THREADS) {
        int n  = idx / D2;
        int d2 = idx - n * D2;
        ull v = *reinterpret_cast<const ull*>(ent + (n0 + n) * EMBED_D + 2 * d2);
        ent_s[d2 * ENT_PITCH + n] = v ^ 0x8000000080000000ULL;  // pre-negate
    }
    for (int idx = tid; idx < TILE_B * D2; idx += THREADS) {
        int b  = idx / D2;
        int d2 = idx - b * D2;
        obj_s[d2 * OBJ_PITCH + b] =
            *reinterpret_cast<const ull*>(g_obj + (b0 + b) * EMBED_D + 2 * d2);
    }
    __syncthreads();

    const int tn   = tid & 31;
    const int wg   = (tid >> 5) & 7;
    const int half = tid >> 8;
    const int d2lo = half * D2_HALF;
    const ull MASK = 0x7FFFFFFF7FFFFFFFULL;

    ull acc[32];
#pragma unroll
    for (int k = 0; k < 32; k++) acc[k] = 0ULL;

    ull t[4];
    unsigned u_lo[4], u_hi[4];
    ull o[8], e[4];

    // ---- peeled first iteration: pipeline fill ----
    {
        const int d2 = d2lo;
#pragma unroll
        for (int i = 0; i < 8; i++) o[i] = obj_s[d2 * OBJ_PITCH + wg + 8 * i];
#pragma unroll
        for (int j = 0; j < 4; j++) e[j] = ent_s[d2 * ENT_PITCH + tn + 32 * j];
#pragma unroll
        for (int k = 0; k < 32; k++) KSTEP(k, (k) >= 2, (k) >= 4);
    }

    // ---- steady state: pipeline carried across iterations ----
#pragma unroll 1
    for (int d2 = d2lo + 1; d2 < d2lo + D2_HALF; d2++) {
#pragma unroll
        for (int i = 0; i < 8; i++) o[i] = obj_s[d2 * OBJ_PITCH + wg + 8 * i];
#pragma unroll
        for (int j = 0; j < 4; j++) e[j] = ent_s[d2 * ENT_PITCH + tn + 32 * j];
#pragma unroll
        for (int k = 0; k < 32; k++) KSTEP(k, true, true);
    }

    // ---- pipeline flush: ANDs for steps 30,31; accs for steps 28..31 ----
    {
        unsigned lo_, hi_;
        ull uu_;
        asm("mov.b64 {%0, %1}, %2;" : "=r"(lo_), "=r"(hi_) : "l"(t[2]));
        asm volatile("and.b32 %0, %1, 0x7fffffff;" : "=r"(u_lo[2]) : "r"(lo_));
        asm volatile("and.b32 %0, %1, 0x7fffffff;" : "=r"(u_hi[2]) : "r"(hi_));
        asm("mov.b64 {%0, %1}, %2;" : "=r"(lo_), "=r"(hi_) : "l"(t[3]));
        asm volatile("and.b32 %0, %1, 0x7fffffff;" : "=r"(u_lo[3]) : "r"(lo_));
        asm volatile("and.b32 %0, %1, 0x7fffffff;" : "=r"(u_hi[3]) : "r"(hi_));
#pragma unroll
        for (int q = 0; q < 4; q++) {
            asm("mov.b64 %0, {%1, %2};" : "=l"(uu_) : "r"(u_lo[q]), "r"(u_hi[q]));
            asm volatile("add.rn.f32x2 %0, %0, %1;" : "+l"(acc[28 + q]) : "l"(uu_));
        }
    }

    // ---- strip: remaining 3 columns (n = 128..130), full D, threads 0..191 ----
    if (tid < TILE_B * 3) {
        int sb = tid / 3;
        int sn = 128 + (tid - sb * 3);
        ull sacc = 0ULL;
#pragma unroll 4
        for (int d2 = 0; d2 < D2; d2++) {
            ull tt = addf2(obj_s[d2 * OBJ_PITCH + sb], ent_s[d2 * ENT_PITCH + sn]) & MASK;
            sacc = addf2(sacc, tt);
        }
        float2 f = *reinterpret_cast<float2*>(&sacc);
        float dist = f.x + f.y;
        out[(b0 + sb) * NUM_ENT + (n0 + sn)] =
            __fdividef(1.0f, 1.0f + __expf(dist - 9.0f));
    }

    // ---- combine halves ----
    __syncthreads();
    ull* part = smem;                      // [32][256] conflict-free (64 KB)
    const int t8 = tid & 255;

    if (half == 1) {
#pragma unroll
        for (int k = 0; k < 32; k++)
            part[k * 256 + t8] = acc[k];
    }
    __syncthreads();

    if (half == 0) {
#pragma unroll
        for (int k = 0; k < 32; k++) {
            int i = k >> 2, j = k & 3;
            int b = b0 + wg + 8 * i;
            ull s = addf2(acc[k], part[k * 256 + t8]);
            float2 f = *reinterpret_cast<float2*>(&s);
            float dist = f.x + f.y;
            out[b * NUM_ENT + (n0 + tn + 32 * j)] =
                __fdividef(1.0f, 1.0f + __expf(dist - 9.0f));
        }
    }
}

extern "C" void kernel_launch(void* const* d_in, const int* in_sizes, int n_in,
                              void* d_out, int out_size) {
    const float* ent   = (const float*)d_in[0];
    const float* rel_e = (const float*)d_in[1];
    const int*   sub   = (const int*)d_in[2];
    const int*   rel   = (const int*)d_in[3];
    float* out = (float*)d_out;

    cudaFuncSetAttribute(transe_kernel,
                         cudaFuncAttributeMaxDynamicSharedMemorySize, SMEM_BYTES);

    obj_kernel<<<(BATCH * EMBED_D + 255) / 256, 256>>>(ent, rel_e, sub, rel);
    transe_kernel<<<dim3(N_TILES, B_TILES), THREADS, SMEM_BYTES>>>(ent, out);
}